// round 4
// baseline (speedup 1.0000x reference)
#include <cuda_runtime.h>
#include <cuda_bf16.h>

// Problem constants (fixed by the reference).
#define B_DIM 64
#define H_DIM 512
#define W_DIM 640
#define P_DIM 100000
#define TOTAL (B_DIM * P_DIM)          // 6,400,000 points
#define HW    (H_DIM * W_DIM)          // 327,680
#define MARGIN_F 1.0f

__global__ void rd_init_out(float* out) {
    if (threadIdx.x == 0) out[0] = 0.0f;
}

__global__ __launch_bounds__(256) void rd_loss_kernel(
    const float* __restrict__ depth,
    const int*   __restrict__ xA,
    const int*   __restrict__ yA,
    const int*   __restrict__ xB,
    const int*   __restrict__ yB,
    const int*   __restrict__ ord,
    float* __restrict__ out)
{
    const float inv_n = 1.0f / (float)TOTAL;
    float acc = 0.0f;

    // 4 points per thread via int4. P % 4 == 0, so the 4 consecutive points
    // of a vec always belong to the same batch -> one divide per vec.
    const int nvec = TOTAL / 4;
    for (int v = blockIdx.x * blockDim.x + threadIdx.x; v < nvec;
         v += gridDim.x * blockDim.x)
    {
        const int idx0 = v * 4;
        const int b = idx0 / P_DIM;
        const float* __restrict__ base = depth + (long long)b * HW;

        const int4 vxA = __ldg((const int4*)(xA)  + v);
        const int4 vyA = __ldg((const int4*)(yA)  + v);
        const int4 vxB = __ldg((const int4*)(xB)  + v);
        const int4 vyB = __ldg((const int4*)(yB)  + v);
        const int4 vod = __ldg((const int4*)(ord) + v);

        const int xa[4] = {vxA.x, vxA.y, vxA.z, vxA.w};
        const int ya[4] = {vyA.x, vyA.y, vyA.z, vyA.w};
        const int xb[4] = {vxB.x, vxB.y, vxB.z, vxB.w};
        const int yb[4] = {vyB.x, vyB.y, vyB.z, vyB.w};
        const int od[4] = {vod.x, vod.y, vod.z, vod.w};

        // Batch the 8 gathers first for MLP (outstanding loads overlap).
        float zA[4], zB[4];
#pragma unroll
        for (int k = 0; k < 4; k++) {
            zA[k] = __ldg(base + ya[k] * W_DIM + xa[k]);
            zB[k] = __ldg(base + yb[k] * W_DIM + xb[k]);
        }

#pragma unroll
        for (int k = 0; k < 4; k++) {
            const float gt   = (float)(od[k] - 1);      // in {-1,0,1}
            const float mask = fabsf(gt);
            const float zd   = zA[k] - zB[k];
            const float t    = fminf(gt * zd, MARGIN_F);
            const float l1   = __logf(1.0f + __expf(-t));
            const float l2   = fmaxf(zd * zd, MARGIN_F * MARGIN_F);
            acc += mask * l1 + (1.0f - mask) * l2;
        }
    }

    // Block reduction: warp shuffle, then smem across warps.
    __shared__ float warp_sums[8];
    const int lane = threadIdx.x & 31;
    const int wid  = threadIdx.x >> 5;
#pragma unroll
    for (int off = 16; off > 0; off >>= 1)
        acc += __shfl_xor_sync(0xFFFFFFFF, acc, off);
    if (lane == 0) warp_sums[wid] = acc;
    __syncthreads();
    if (wid == 0) {
        float s = (lane < (blockDim.x >> 5)) ? warp_sums[lane] : 0.0f;
#pragma unroll
        for (int off = 4; off > 0; off >>= 1)
            s += __shfl_xor_sync(0xFFFFFFFF, s, off);
        if (lane == 0) atomicAdd(out, s * inv_n);
    }
}

extern "C" void kernel_launch(void* const* d_in, const int* in_sizes, int n_in,
                              void* d_out, int out_size)
{
    const float* depth = (const float*)d_in[0];
    const int*   xA    = (const int*)d_in[1];
    const int*   yA    = (const int*)d_in[2];
    const int*   xB    = (const int*)d_in[3];
    const int*   yB    = (const int*)d_in[4];
    const int*   ord   = (const int*)d_in[5];
    float* out = (float*)d_out;

    rd_init_out<<<1, 32>>>(out);

    const int threads = 256;
    const int nvec = TOTAL / 4;                       // 1,600,000
    int blocks = (nvec + threads - 1) / threads;      // 6250
    rd_loss_kernel<<<blocks, threads>>>(depth, xA, yA, xB, yB, ord, out);
}

// round 5
// speedup vs baseline: 1.0702x; 1.0702x over previous
#include <cuda_runtime.h>
#include <cuda_bf16.h>

// Problem constants (fixed by the reference).
#define B_DIM   64
#define H_DIM   512
#define W_DIM   640
#define P_DIM   100000
#define TOTAL   (B_DIM * P_DIM)     // 6,400,000 points
#define HW      (H_DIM * W_DIM)     // 327,680
#define NV4     (TOTAL / 4)         // 1,600,000 vec4 groups
#define HALF    (NV4 / 2)           // 800,000 threads
#define THREADS 256
#define BLOCKS  (HALF / THREADS)    // 3125 (exact)

// Cross-launch scratch for single-kernel finalization. Statically zero.
__device__ float        g_partial = 0.0f;
__device__ unsigned int g_done    = 0u;

__device__ __forceinline__ float loss_pt(float za, float zb, int od) {
    const float zd = za - zb;
    // gt = od-1 in {-1,0,1}; sign only matters when od != 1.
    const float t  = fminf((od >= 2) ? zd : -zd, 1.0f);
    const float l1 = __logf(1.0f + __expf(-t));
    const float l2 = fmaxf(zd * zd, 1.0f);
    return (od == 1) ? l2 : l1;
}

__global__ __launch_bounds__(THREADS) void rd_loss_kernel(
    const float* __restrict__ depth,
    const int*   __restrict__ xA,
    const int*   __restrict__ yA,
    const int*   __restrict__ xB,
    const int*   __restrict__ yB,
    const int*   __restrict__ ord,
    float* __restrict__ out)
{
    const int t  = blockIdx.x * THREADS + threadIdx.x;
    const int v0 = t;            // first vec4 group
    const int v1 = t + HALF;     // second vec4 group (coalesced within warp)

    // ---- Issue ALL index loads first (10 coalesced int4 LDGs in flight) ----
    const int4 xa0 = __ldg((const int4*)xA  + v0);
    const int4 ya0 = __ldg((const int4*)yA  + v0);
    const int4 xb0 = __ldg((const int4*)xB  + v0);
    const int4 yb0 = __ldg((const int4*)yB  + v0);
    const int4 od0 = __ldg((const int4*)ord + v0);
    const int4 xa1 = __ldg((const int4*)xA  + v1);
    const int4 ya1 = __ldg((const int4*)yA  + v1);
    const int4 xb1 = __ldg((const int4*)xB  + v1);
    const int4 yb1 = __ldg((const int4*)yB  + v1);
    const int4 od1 = __ldg((const int4*)ord + v1);

    // Batch index per group (4 consecutive points share a batch; P % 4 == 0).
    const float* __restrict__ base0 = depth + (long long)((v0 * 4) / P_DIM) * HW;
    const float* __restrict__ base1 = depth + (long long)((v1 * 4) / P_DIM) * HW;

    // ---- Issue ALL 16 gathers batched (max MLP) ----
    float zA[8], zB[8];
    zA[0] = __ldg(base0 + ya0.x * W_DIM + xa0.x);
    zA[1] = __ldg(base0 + ya0.y * W_DIM + xa0.y);
    zA[2] = __ldg(base0 + ya0.z * W_DIM + xa0.z);
    zA[3] = __ldg(base0 + ya0.w * W_DIM + xa0.w);
    zA[4] = __ldg(base1 + ya1.x * W_DIM + xa1.x);
    zA[5] = __ldg(base1 + ya1.y * W_DIM + xa1.y);
    zA[6] = __ldg(base1 + ya1.z * W_DIM + xa1.z);
    zA[7] = __ldg(base1 + ya1.w * W_DIM + xa1.w);
    zB[0] = __ldg(base0 + yb0.x * W_DIM + xb0.x);
    zB[1] = __ldg(base0 + yb0.y * W_DIM + xb0.y);
    zB[2] = __ldg(base0 + yb0.z * W_DIM + xb0.z);
    zB[3] = __ldg(base0 + yb0.w * W_DIM + xb0.w);
    zB[4] = __ldg(base1 + yb1.x * W_DIM + xb1.x);
    zB[5] = __ldg(base1 + yb1.y * W_DIM + xb1.y);
    zB[6] = __ldg(base1 + yb1.z * W_DIM + xb1.z);
    zB[7] = __ldg(base1 + yb1.w * W_DIM + xb1.w);

    // ---- Loss ----
    float acc = 0.0f;
    acc += loss_pt(zA[0], zB[0], od0.x);
    acc += loss_pt(zA[1], zB[1], od0.y);
    acc += loss_pt(zA[2], zB[2], od0.z);
    acc += loss_pt(zA[3], zB[3], od0.w);
    acc += loss_pt(zA[4], zB[4], od1.x);
    acc += loss_pt(zA[5], zB[5], od1.y);
    acc += loss_pt(zA[6], zB[6], od1.z);
    acc += loss_pt(zA[7], zB[7], od1.w);

    // ---- Block reduction: warp shuffle, then smem across warps ----
    __shared__ float warp_sums[THREADS / 32];
    const int lane = threadIdx.x & 31;
    const int wid  = threadIdx.x >> 5;
#pragma unroll
    for (int off = 16; off > 0; off >>= 1)
        acc += __shfl_xor_sync(0xFFFFFFFF, acc, off);
    if (lane == 0) warp_sums[wid] = acc;
    __syncthreads();

    if (threadIdx.x == 0) {
        float s = 0.0f;
#pragma unroll
        for (int w = 0; w < THREADS / 32; w++) s += warp_sums[w];

        // Accumulate into device scratch; last block finalizes and resets
        // the scratch so every graph replay starts from a clean state.
        atomicAdd(&g_partial, s);
        __threadfence();
        const unsigned done = atomicInc(&g_done, BLOCKS - 1);  // wraps to 0
        if (done == BLOCKS - 1) {
            const float total = atomicAdd(&g_partial, 0.0f);   // coherent read
            out[0] = total * (1.0f / (float)TOTAL);
            g_partial = 0.0f;                                  // reset for next replay
        }
    }
}

extern "C" void kernel_launch(void* const* d_in, const int* in_sizes, int n_in,
                              void* d_out, int out_size)
{
    const float* depth = (const float*)d_in[0];
    const int*   xA    = (const int*)d_in[1];
    const int*   yA    = (const int*)d_in[2];
    const int*   xB    = (const int*)d_in[3];
    const int*   yB    = (const int*)d_in[4];
    const int*   ord   = (const int*)d_in[5];
    float* out = (float*)d_out;

    rd_loss_kernel<<<BLOCKS, THREADS>>>(depth, xA, yA, xB, yB, ord, out);
}